// round 3
// baseline (speedup 1.0000x reference)
#include <cuda_runtime.h>
#include <cuda_bf16.h>

// Skewed L1 loss mean reduction, single-kernel decoupled reduction.
// lam(y) with LIM=(0,1), MEDIAN=0.5, LMAX=1 simplifies to 2y-1 on both branches.
// term = |p - t| * exp(sign(t - p) * (2t - 1));  output = mean(term).

#define NBLOCKS (148 * 8)
#define NTHREADS 256

__device__ float g_block_sums[NBLOCKS];
__device__ unsigned int g_ticket = 0;   // reset to 0 by last block each launch

__device__ __forceinline__ float skew_term(float p, float t) {
    float d = p - t;
    float lam = 2.0f * t - 1.0f;
    float e = (d <= 0.0f) ? lam : -lam;
    return fabsf(d) * __expf(e);
}

__device__ __forceinline__ float block_reduce(float acc, float* warp_sums) {
    #pragma unroll
    for (int off = 16; off > 0; off >>= 1)
        acc += __shfl_xor_sync(0xFFFFFFFF, acc, off);
    int lane = threadIdx.x & 31;
    int wid  = threadIdx.x >> 5;
    if (lane == 0) warp_sums[wid] = acc;
    __syncthreads();
    float v = 0.0f;
    if (wid == 0) {
        v = (lane < (NTHREADS / 32)) ? warp_sums[lane] : 0.0f;
        #pragma unroll
        for (int off = 4; off > 0; off >>= 1)
            v += __shfl_xor_sync(0xFFFFFFFF, v, off);
    }
    return v;  // valid in warp 0
}

__global__ __launch_bounds__(NTHREADS) void skewed_loss_kernel(
    const float* __restrict__ y_pred,
    const float* __restrict__ y_true,
    float* __restrict__ out,
    int n4,          // number of float4 chunks
    float inv_n)
{
    const float4* p4 = reinterpret_cast<const float4*>(y_pred);
    const float4* t4 = reinterpret_cast<const float4*>(y_true);

    const int stride = NBLOCKS * NTHREADS;
    float acc = 0.0f;

    int i = blockIdx.x * NTHREADS + threadIdx.x;

    // Unrolled by 2: 4 batched LDG.128 at loop head for deeper MLP.
    for (; i + stride < n4; i += 2 * stride) {
        float4 p0 = __ldcs(p4 + i);
        float4 t0 = __ldcs(t4 + i);
        float4 p1 = __ldcs(p4 + i + stride);
        float4 t1 = __ldcs(t4 + i + stride);

        acc += skew_term(p0.x, t0.x);
        acc += skew_term(p0.y, t0.y);
        acc += skew_term(p0.z, t0.z);
        acc += skew_term(p0.w, t0.w);
        acc += skew_term(p1.x, t1.x);
        acc += skew_term(p1.y, t1.y);
        acc += skew_term(p1.z, t1.z);
        acc += skew_term(p1.w, t1.w);
    }
    for (; i < n4; i += stride) {
        float4 p = __ldcs(p4 + i);
        float4 t = __ldcs(t4 + i);
        acc += skew_term(p.x, t.x);
        acc += skew_term(p.y, t.y);
        acc += skew_term(p.z, t.z);
        acc += skew_term(p.w, t.w);
    }

    __shared__ float warp_sums[NTHREADS / 32];
    float bsum = block_reduce(acc, warp_sums);

    __shared__ unsigned int s_ticket;
    if (threadIdx.x == 0) {
        g_block_sums[blockIdx.x] = bsum;
        __threadfence();
        s_ticket = atomicAdd(&g_ticket, 1u);
    }
    __syncthreads();

    // Last block to arrive performs the final reduction.
    if (s_ticket == NBLOCKS - 1) {
        float v = 0.0f;
        for (int j = threadIdx.x; j < NBLOCKS; j += NTHREADS)
            v += g_block_sums[j];
        __shared__ float warp_sums2[NTHREADS / 32];
        float total = block_reduce(v, warp_sums2);
        if (threadIdx.x == 0) {
            out[0] = total * inv_n;
            g_ticket = 0;   // reset for next (graph-replayed) launch
        }
    }
}

extern "C" void kernel_launch(void* const* d_in, const int* in_sizes, int n_in,
                              void* d_out, int out_size) {
    const float* y_pred = (const float*)d_in[0];
    const float* y_true = (const float*)d_in[1];
    float* out = (float*)d_out;

    int n = in_sizes[0];          // 33554432, divisible by 4
    int n4 = n >> 2;
    float inv_n = 1.0f / (float)n;

    skewed_loss_kernel<<<NBLOCKS, NTHREADS>>>(y_pred, y_true, out, n4, inv_n);
}

// round 6
// speedup vs baseline: 1.1864x; 1.1864x over previous
#include <cuda_runtime.h>
#include <cuda_bf16.h>

// Skewed L1 loss mean reduction, single-kernel decoupled reduction.
// lam(y) with LIM=(0,1), MEDIAN=0.5, LMAX=1 simplifies to 2y-1 on both branches.
// term = |p - t| * exp(sign(t - p) * (2t - 1));  output = mean(term).

#define NBLOCKS (148 * 8)
#define NTHREADS 256

__device__ float g_block_sums[NBLOCKS];
__device__ unsigned int g_ticket = 0;   // reset to 0 by last block each launch

__device__ __forceinline__ float block_reduce(float acc, float* warp_sums) {
    #pragma unroll
    for (int off = 16; off > 0; off >>= 1)
        acc += __shfl_xor_sync(0xFFFFFFFF, acc, off);
    int lane = threadIdx.x & 31;
    int wid  = threadIdx.x >> 5;
    if (lane == 0) warp_sums[wid] = acc;
    __syncthreads();
    float v = 0.0f;
    if (wid == 0) {
        v = (lane < (NTHREADS / 32)) ? warp_sums[lane] : 0.0f;
        #pragma unroll
        for (int off = 4; off > 0; off >>= 1)
            v += __shfl_xor_sync(0xFFFFFFFF, v, off);
    }
    return v;  // valid in warp 0
}

__global__ __launch_bounds__(NTHREADS, 8) void skewed_loss_kernel(
    const float* __restrict__ y_pred,
    const float* __restrict__ y_true,
    float* __restrict__ out,
    int n4,          // number of float4 chunks
    float inv_n)
{
    const float4* p4 = reinterpret_cast<const float4*>(y_pred);
    const float4* t4 = reinterpret_cast<const float4*>(y_true);

    float acc = 0.0f;
    const int stride = NBLOCKS * NTHREADS;
    for (int i = blockIdx.x * NTHREADS + threadIdx.x; i < n4; i += stride) {
        float4 p = p4[i];
        float4 t = t4[i];

        {
            float d = p.x - t.x;
            float lam = 2.0f * t.x - 1.0f;
            float e = (d <= 0.0f) ? lam : -lam;
            acc += fabsf(d) * __expf(e);
        }
        {
            float d = p.y - t.y;
            float lam = 2.0f * t.y - 1.0f;
            float e = (d <= 0.0f) ? lam : -lam;
            acc += fabsf(d) * __expf(e);
        }
        {
            float d = p.z - t.z;
            float lam = 2.0f * t.z - 1.0f;
            float e = (d <= 0.0f) ? lam : -lam;
            acc += fabsf(d) * __expf(e);
        }
        {
            float d = p.w - t.w;
            float lam = 2.0f * t.w - 1.0f;
            float e = (d <= 0.0f) ? lam : -lam;
            acc += fabsf(d) * __expf(e);
        }
    }

    __shared__ float warp_sums[NTHREADS / 32];
    float bsum = block_reduce(acc, warp_sums);

    __shared__ unsigned int s_ticket;
    if (threadIdx.x == 0) {
        g_block_sums[blockIdx.x] = bsum;
        __threadfence();
        s_ticket = atomicAdd(&g_ticket, 1u);
    }
    __syncthreads();

    // Last block to arrive performs the final reduction.
    if (s_ticket == NBLOCKS - 1) {
        float v = 0.0f;
        for (int j = threadIdx.x; j < NBLOCKS; j += NTHREADS)
            v += g_block_sums[j];
        __shared__ float warp_sums2[NTHREADS / 32];
        float total = block_reduce(v, warp_sums2);
        if (threadIdx.x == 0) {
            out[0] = total * inv_n;
            g_ticket = 0;   // reset for next (graph-replayed) launch
        }
    }
}

extern "C" void kernel_launch(void* const* d_in, const int* in_sizes, int n_in,
                              void* d_out, int out_size) {
    const float* y_pred = (const float*)d_in[0];
    const float* y_true = (const float*)d_in[1];
    float* out = (float*)d_out;

    int n = in_sizes[0];          // 33554432, divisible by 4
    int n4 = n >> 2;
    float inv_n = 1.0f / (float)n;

    skewed_loss_kernel<<<NBLOCKS, NTHREADS>>>(y_pred, y_true, out, n4, inv_n);
}